// round 17
// baseline (speedup 1.0000x reference)
#include <cuda_runtime.h>
#include <cstdint>

#define NUM_EXPERTS 64
#define TOP_K 4
#define EMA_DECAY 0.99f
#define NBINS (NUM_EXPERTS * NUM_EXPERTS)
#define NCTAS 148             // 1 CTA/SM
#define NTHREADS 1024
#define STRIDE (NCTAS * NTHREADS)
#define BATCH 6               // tokens per wait
#define NSLOTS (2 * BATCH)    // double-buffered slot slabs
#define SLAB (NTHREADS * 16)  // 16 KB per slot slab

// dynamic SMEM: histogram + 12 slot slabs
#define OFF_SP 0
#define OFF_RING (NBINS * 4)                        // 16 KB
#define OFF_ISLAST (OFF_RING + NSLOTS * SLAB)       // 16 + 192 KB
#define DSMEM_TOTAL (OFF_ISLAST + 64)

// Ordered-pair histogram scratch: P[a*64+b] over tokens, pairs (k1<k2).
// Symmetric coact = P + P^T.
// INVARIANT at kernel entry: g_P == 0, g_done == 0.
__device__ unsigned int g_P[NBINS];
__device__ unsigned int g_done;

__device__ __forceinline__ uint32_t smem_addr_u32(const void* p) {
    uint32_t a;
    asm("{ .reg .u64 t; cvta.to.shared.u64 t, %1; cvt.u32.u64 %0, t; }"
        : "=r"(a) : "l"(p));
    return a;
}
__device__ __forceinline__ void red_shared_inc(uint32_t byte_addr) {
    asm volatile("red.shared.add.u32 [%0], %1;" :: "r"(byte_addr), "r"(1u) : "memory");
}
__device__ __forceinline__ void red_global_add(unsigned int* p, unsigned int v) {
    asm volatile("red.global.add.u32 [%0], %1;" :: "l"(p), "r"(v) : "memory");
}
__device__ __forceinline__ void cp_async16(uint32_t smem_dst, const void* gsrc) {
    asm volatile("cp.async.cg.shared.global [%0], [%1], 16;"
                 :: "r"(smem_dst), "l"(gsrc) : "memory");
}
#define CP_COMMIT()  asm volatile("cp.async.commit_group;" ::: "memory")
#define CP_WAIT_1()  asm volatile("cp.async.wait_group 1;" ::: "memory")
#define CP_WAIT_0()  asm volatile("cp.async.wait_group 0;" ::: "memory")
__device__ __forceinline__ int4 lds128(uint32_t addr) {
    int4 v;
    asm volatile("ld.shared.v4.b32 {%0,%1,%2,%3}, [%4];"
                 : "=r"(v.x), "=r"(v.y), "=r"(v.z), "=r"(v.w) : "r"(addr));
    return v;
}

// 6 pair-REDs for one token. Byte offsets: ((x<<6)+y)<<2 = (x<<8)+(y<<2).
__device__ __forceinline__ void token_pairs(uint32_t sbase, int4 v) {
    uint32_t r0 = (uint32_t)v.x << 8, r1 = (uint32_t)v.y << 8, r2 = (uint32_t)v.z << 8;
    uint32_t c1 = (uint32_t)v.y << 2, c2 = (uint32_t)v.z << 2, c3 = (uint32_t)v.w << 2;
    red_shared_inc(sbase + r0 + c1);
    red_shared_inc(sbase + r0 + c2);
    red_shared_inc(sbase + r0 + c3);
    red_shared_inc(sbase + r1 + c2);
    red_shared_inc(sbase + r1 + c3);
    red_shared_inc(sbase + r2 + c3);
}

// Fill one 6-slot batch (clamped OOB sources; extras never processed).
__device__ __forceinline__ void fill_batch(uint32_t ring_tid, unsigned bufsel,
                                           const int4* __restrict__ idx,
                                           unsigned g0, unsigned i0, unsigned last) {
    uint32_t dst = ring_tid + bufsel * (BATCH * SLAB);
    #pragma unroll
    for (unsigned s = 0; s < BATCH; s++) {
        unsigned t = g0 + (i0 + s) * STRIDE;
        cp_async16(dst + s * SLAB, idx + (t > last ? last : t));
    }
    CP_COMMIT();
}

// ---------------------------------------------------------------------------
// Fused kernel: batched per-thread cp.async double-buffer, ONE wait per
// 6 tokens (amortizes LSU-queue latency over a whole batch of REDs).
// No CTA barriers in the main loop.
// ---------------------------------------------------------------------------
__global__ void __launch_bounds__(NTHREADS, 1)
fused_tracker_kernel(const int4* __restrict__ idx,
                     const float* __restrict__ ema_in,
                     const float* __restrict__ coact_in,
                     float* __restrict__ out,
                     unsigned ntok) {
    extern __shared__ char dsm[];
    unsigned int* sP = (unsigned int*)(dsm + OFF_SP);
    const unsigned tid = threadIdx.x;

    for (int i = tid; i < NBINS; i += NTHREADS) sP[i] = 0u;

    const uint32_t sbase    = smem_addr_u32(sP);
    const uint32_t ring_tid = smem_addr_u32(dsm + OFF_RING) + tid * 16u;

    const unsigned g0   = blockIdx.x * NTHREADS + tid;
    const unsigned last = ntok - 1u;
    const unsigned nIter = (ntok - g0 + STRIDE - 1u) / STRIDE;  // >=1 per thread

    // prologue: fill both batches
    fill_batch(ring_tid, 0u, idx, g0, 0u, last);
    fill_batch(ring_tid, 1u, idx, g0, BATCH, last);
    __syncthreads();   // sP zero-init visible before first RED

    unsigned bufsel = 0;
    for (unsigned base = 0; base < nIter; base += BATCH) {
        CP_WAIT_1();   // oldest group (this batch's fill) complete

        uint32_t src = ring_tid + bufsel * (BATCH * SLAB);
        unsigned rem = nIter - base;
        if (rem >= BATCH) {
            // fast path: front-batch all 6 LDS.128, then 36 REDs
            int4 v0 = lds128(src + 0 * SLAB);
            int4 v1 = lds128(src + 1 * SLAB);
            int4 v2 = lds128(src + 2 * SLAB);
            int4 v3 = lds128(src + 3 * SLAB);
            int4 v4 = lds128(src + 4 * SLAB);
            int4 v5 = lds128(src + 5 * SLAB);
            // refill this buffer with tokens base+2*BATCH.. while REDs run
            fill_batch(ring_tid, bufsel, idx, g0, base + 2u * BATCH, last);
            token_pairs(sbase, v0);
            token_pairs(sbase, v1);
            token_pairs(sbase, v2);
            token_pairs(sbase, v3);
            token_pairs(sbase, v4);
            token_pairs(sbase, v5);
        } else {
            CP_COMMIT();   // keep group accounting aligned (empty group)
            for (unsigned s = 0; s < rem; s++)
                token_pairs(sbase, lds128(src + s * SLAB));
        }
        bufsel ^= 1u;
    }
    CP_WAIT_0();       // retire outstanding groups
    __syncthreads();   // drain pending shared reductions

    // --- flush CTA-local histogram to global scratch (REDG, no return) ---
    for (int i = tid; i < NBINS; i += NTHREADS) {
        unsigned v = sP[i];
        if (v) red_global_add(&g_P[i], v);
    }

    // --- last-CTA election (atomicInc self-wraps to 0 for next replay) ---
    __threadfence();
    __syncthreads();
    unsigned* isLast = (unsigned*)(dsm + OFF_ISLAST);
    if (tid == 0)
        *isLast = (atomicInc(&g_done, gridDim.x - 1u) == gridDim.x - 1u) ? 1u : 0u;
    __syncthreads();
    if (!*isLast) return;

    // --- finalize (last CTA): stage g_P -> sP, zero g_P for next replay ---
    for (int i = tid; i < NBINS; i += NTHREADS) {
        unsigned v = __ldcg(&g_P[i]);
        sP[i] = v;
        g_P[i] = 0u;
    }
    __syncthreads();

    // coact output: coact_in + P + P^T   (integer-exact in fp32)
    for (int i = tid; i < NBINS; i += NTHREADS) {
        int a = i >> 6;
        int b = i & 63;
        out[NUM_EXPERTS + i] =
            coact_in[i] + (float)(sP[(a << 6) + b] + sP[(b << 6) + a]);
    }

    // load EMA: 3*count[e] = rowsum(P)[e] + colsum(P)[e]
    if (tid < NUM_EXPERTS) {
        int e = tid;
        unsigned s = 0u;
        #pragma unroll
        for (int j = 0; j < NUM_EXPERTS; j++) {
            s += sP[(e << 6) + j];
            s += sP[(j << 6) + e];
        }
        float count = (float)(s / 3u);          // exactly divisible by 3
        float load = count / (float)ntok;
        out[e] = ema_in[e] * EMA_DECAY + load * (1.0f - EMA_DECAY);
    }
}

// ---------------------------------------------------------------------------
// kernel_launch: ONE launch, graph-capturable, alloc-free.
// Inputs (metadata order):
//   d_in[0] expert_indices        int32  [N,4]
//   d_in[1] expert_weights        f32    [N,4]   (UNUSED by reference)
//   d_in[2] expert_load_ema       f32    [64]
//   d_in[3] expert_pair_coact     f32    [64,64]
// Output: f32 [64 + 4096] = (new_load_ema, new_coact) concatenated.
// ---------------------------------------------------------------------------
extern "C" void kernel_launch(void* const* d_in, const int* in_sizes, int n_in,
                              void* d_out, int out_size) {
    const int4* idx       = (const int4*)d_in[0];
    const float* ema_in   = (const float*)d_in[2];
    const float* coact_in = (const float*)d_in[3];
    float* out = (float*)d_out;

    unsigned ntok = (unsigned)(in_sizes[0] / TOP_K);

    cudaFuncSetAttribute(fused_tracker_kernel,
                         cudaFuncAttributeMaxDynamicSharedMemorySize, DSMEM_TOTAL);

    fused_tracker_kernel<<<NCTAS, NTHREADS, DSMEM_TOTAL>>>(idx, ema_in, coact_in, out, ntok);
}